// round 15
// baseline (speedup 1.0000x reference)
#include <cuda_runtime.h>

#define H     51
#define BB    8
#define TPB   384
#define NCTA  128
#define T_IN  512
#define T_FUT 64
#define T_TOT 576
#define NTICK 514

typedef unsigned long long ull;

struct __align__(16) Smem {
    float4     W1q[52][H];    // k=0: W_ih1; k=1..51: W_hh1 col k-1; (i,f,g,o) of unit j
    float4     W2q[102][H];   // k=0..50: W_ih2; 51..101: W_hh2
    float4     W3q[102][H];
    ulonglong2 bq[3][H];      // bias pairs {bi,bf},{bg,bo}
    ull        hdup[154][BB]; // {h,h} pairs; row0=x, 1..51=h1, 52..102=h2, 103..153=h3
    float      wlin[52];
    float      blin;
};

__device__ __forceinline__ ull pack2(float x) {
    ull r; asm("mov.b64 %0, {%1, %1};" : "=l"(r) : "f"(x)); return r;
}
__device__ __forceinline__ ull packf2(float a, float b) {
    ull r; asm("mov.b64 %0, {%1, %2};" : "=l"(r) : "f"(a), "f"(b)); return r;
}
__device__ __forceinline__ void unpack2(ull v, float &a, float &b) {
    asm("mov.b64 {%0, %1}, %2;" : "=f"(a), "=f"(b) : "l"(v));
}
__device__ __forceinline__ ull fma2(ull a, ull b, ull c) {
    ull d; asm("fma.rn.f32x2 %0, %1, %2, %3;" : "=l"(d) : "l"(a), "l"(b), "l"(c)); return d;
}
__device__ __forceinline__ ull add2(ull a, ull b) {
    ull d; asm("add.rn.f32x2 %0, %1, %2;" : "=l"(d) : "l"(a), "l"(b)); return d;
}
// hardware tanh (sm_75+): 1 MUFU op, rel err ~2^-11
__device__ __forceinline__ float tanh_(float x) {
    float y; asm("tanh.approx.f32 %0, %1;" : "=f"(y) : "f"(x)); return y;
}
__device__ __forceinline__ float sigf(float x) {
    return fmaf(tanh_(0.5f * x), 0.5f, 0.5f);
}

// K/2 iterations; each: 1 weight LDS.128 + 4 state LDS.128 + 16 fma2 (all 8 batch)
// acc[b]   = {i_b, f_b}  (b = 0..7)
// acc[8+b] = {g_b, o_b}
template <int KH>
__device__ __forceinline__ void gloop2(const float4 (*__restrict__ W)[H],
                                       const ull (*__restrict__ Vd)[BB],
                                       int j, int kbase, ull acc[16]) {
#pragma unroll 3
    for (int k = 0; k < KH; k++) {
        ulonglong2 wv = *(const ulonglong2 *)&W[kbase + k][j];   // {wi,wf},{wg,wo}
        ulonglong2 h0 = *(const ulonglong2 *)&Vd[kbase + k][0];
        ulonglong2 h1 = *(const ulonglong2 *)&Vd[kbase + k][2];
        ulonglong2 h2 = *(const ulonglong2 *)&Vd[kbase + k][4];
        ulonglong2 h3 = *(const ulonglong2 *)&Vd[kbase + k][6];
        acc[0]  = fma2(wv.x, h0.x, acc[0]);  acc[1]  = fma2(wv.x, h0.y, acc[1]);
        acc[2]  = fma2(wv.x, h1.x, acc[2]);  acc[3]  = fma2(wv.x, h1.y, acc[3]);
        acc[4]  = fma2(wv.x, h2.x, acc[4]);  acc[5]  = fma2(wv.x, h2.y, acc[5]);
        acc[6]  = fma2(wv.x, h3.x, acc[6]);  acc[7]  = fma2(wv.x, h3.y, acc[7]);
        acc[8]  = fma2(wv.y, h0.x, acc[8]);  acc[9]  = fma2(wv.y, h0.y, acc[9]);
        acc[10] = fma2(wv.y, h1.x, acc[10]); acc[11] = fma2(wv.y, h1.y, acc[11]);
        acc[12] = fma2(wv.y, h2.x, acc[12]); acc[13] = fma2(wv.y, h2.y, acc[13]);
        acc[14] = fma2(wv.y, h3.x, acc[14]); acc[15] = fma2(wv.y, h3.y, acc[15]);
    }
}

// combine k-half partials with adjacent lane (both lanes end with full sums)
__device__ __forceinline__ void combine(ull acc[16]) {
#pragma unroll
    for (int i = 0; i < 16; i++)
        acc[i] = add2(acc[i], __shfl_xor_sync(0xffffffffu, acc[i], 1));
}

// cell for 4 batch elems starting at compile-time base (0 or 4)
template <int BASE>
__device__ __forceinline__ void cellh(const ull acc[16], float creg[4], ull hnew[4]) {
#pragma unroll
    for (int b = 0; b < 4; b++) {
        float iv, fv, gv, ov;
        unpack2(acc[BASE + b],     iv, fv);
        unpack2(acc[8 + BASE + b], gv, ov);
        float cn = sigf(fv) * creg[b] + sigf(iv) * tanh_(gv);
        float hn = sigf(ov) * tanh_(cn);
        creg[b]  = cn;
        hnew[b]  = pack2(hn);
    }
}

__device__ __forceinline__ void hwrite(ull *dst, const ull hnew[4]) {
    ulonglong2 v0, v1;
    v0.x = hnew[0]; v0.y = hnew[1];
    v1.x = hnew[2]; v1.y = hnew[3];
    *(ulonglong2 *)dst       = v0;
    *(ulonglong2 *)(dst + 2) = v1;
}

__device__ __forceinline__ float head_dot(const Smem *s, int b) {
    float sum = s->blin;
#pragma unroll 3
    for (int jj = 0; jj < H; jj++)
        sum = fmaf(s->wlin[jj], ((const float *)&s->hdup[103 + jj][b])[0], sum);
    return sum;
}

__global__ void __launch_bounds__(TPB, 1)
lstm_seq_kernel(const float *__restrict__ input,
                const float *__restrict__ W_ih1, const float *__restrict__ W_hh1,
                const float *__restrict__ b_ih1, const float *__restrict__ b_hh1,
                const float *__restrict__ W_ih2, const float *__restrict__ W_hh2,
                const float *__restrict__ b_ih2, const float *__restrict__ b_hh2,
                const float *__restrict__ W_ih3, const float *__restrict__ W_hh3,
                const float *__restrict__ b_ih3, const float *__restrict__ b_hh3,
                const float *__restrict__ W_lin, const float *__restrict__ b_lin,
                float *__restrict__ out) {
    extern __shared__ char raw[];
    Smem *s = (Smem *)raw;

    const int tid = threadIdx.x;
    const int b0  = blockIdx.x * BB;
    const int L   = tid >> 7;       // layer block: warps 0-3 / 4-7 / 8-11
    const int l   = tid & 127;
    const bool gate_lane = (l < 102);
    const int  j     = gate_lane ? (l >> 1) : (H - 1);  // hidden unit
    const int  khalf = l & 1;                           // k-half; owns batch 4*khalf..+3
    const bool head_lane = (L == 0) && (l >= 102) && (l < 102 + BB);
    const bool xf_lane   = (L == 1) && (l >= 102) && (l < 102 + BB);

    // ---- one-time staging: weight quads (i,f,g,o) per unit j ----
    for (int idx = tid; idx < 52 * H; idx += TPB) {
        int k = idx / H, jj = idx % H;
        float4 v;
        if (k == 0)
            v = make_float4(W_ih1[jj], W_ih1[jj + 51], W_ih1[jj + 102], W_ih1[jj + 153]);
        else
            v = make_float4(W_hh1[jj * H + k - 1],         W_hh1[(jj + 51) * H + k - 1],
                            W_hh1[(jj + 102) * H + k - 1], W_hh1[(jj + 153) * H + k - 1]);
        s->W1q[k][jj] = v;
    }
    for (int idx = tid; idx < 102 * H; idx += TPB) {
        int k = idx / H, jj = idx % H;
        int kk = (k < H) ? k : k - H;
        const float *s2 = (k < H) ? W_ih2 : W_hh2;
        const float *s3 = (k < H) ? W_ih3 : W_hh3;
        s->W2q[k][jj] = make_float4(s2[jj * H + kk],         s2[(jj + 51) * H + kk],
                                    s2[(jj + 102) * H + kk], s2[(jj + 153) * H + kk]);
        s->W3q[k][jj] = make_float4(s3[jj * H + kk],         s3[(jj + 51) * H + kk],
                                    s3[(jj + 102) * H + kk], s3[(jj + 153) * H + kk]);
    }
    for (int idx = tid; idx < 3 * H; idx += TPB) {
        int ly = idx / H, jj = idx % H;
        const float *bi = (ly == 0) ? b_ih1 : (ly == 1) ? b_ih2 : b_ih3;
        const float *bh = (ly == 0) ? b_hh1 : (ly == 1) ? b_hh2 : b_hh3;
        ulonglong2 bv;
        bv.x = packf2(bi[jj] + bh[jj],             bi[jj + 51] + bh[jj + 51]);
        bv.y = packf2(bi[jj + 102] + bh[jj + 102], bi[jj + 153] + bh[jj + 153]);
        s->bq[ly][jj] = bv;
    }
    if (tid < H) s->wlin[tid] = W_lin[tid];
    if (tid == 0) s->blin = b_lin[0];
    for (int idx = tid; idx < 153 * BB; idx += TPB) (&s->hdup[1][0])[idx] = 0ull;
    if (tid < BB) s->hdup[0][tid] = pack2(input[(size_t)(b0 + tid) * T_IN]);  // x(0)
    __syncthreads();

    float creg[4] = {0.f, 0.f, 0.f, 0.f};   // c for batch 4*khalf .. +3

    // ===== pipelined main loop: tick t -> L1@t, L2@t-1, L3@t-2 =====
    for (int t = 0; t < NTICK; t++) {
        ull   acc[16] = {};
        ull   hnew[4];
        float xr = 0.0f;
        const bool valid = gate_lane &&
            ((L == 0) ? (t <= T_IN - 1)
                      : (L == 1) ? (t >= 1 && t <= T_IN) : (t >= 2));
        if (gate_lane) {
            if (khalf == 0) {
                ulonglong2 bv = s->bq[L][j];
#pragma unroll
                for (int i = 0; i < 8; i++) { acc[i] = bv.x; acc[8 + i] = bv.y; }
            }
            if (L == 0)      gloop2<26>(s->W1q,  s->hdup,      j, khalf * 26, acc);
            else if (L == 1) gloop2<51>(s->W2q,  s->hdup + 1,  j, khalf * 51, acc);
            else             gloop2<51>(s->W3q,  s->hdup + 52, j, khalf * 51, acc);
        } else if (head_lane && t >= 3) {
            int b = l - 102;
            out[(size_t)(b0 + b) * T_TOT + (t - 3)] = head_dot(s, b);
        } else if (xf_lane && t + 1 < T_IN) {
            xr = input[(size_t)(b0 + l - 102) * T_IN + t + 1];
        }
        combine(acc);
        if (valid) {
            if (khalf == 0) cellh<0>(acc, creg, hnew);
            else            cellh<4>(acc, creg, hnew);
        }
        __syncthreads();
        if (valid) hwrite(&s->hdup[1 + L * H + j][khalf * 4], hnew);
        if (xf_lane && t + 1 < T_IN) s->hdup[0][l - 102] = pack2(xr);
        __syncthreads();
    }

    // ---- drain: out(511) + first autoregressive input ----
    if (tid < BB) {
        float v = head_dot(s, tid);
        out[(size_t)(b0 + tid) * T_TOT + (T_IN - 1)] = v;
        s->hdup[0][tid] = pack2(v);
    }
    __syncthreads();

    // ===== autoregressive future: layer-serial, same machinery =====
    for (int fs = 0; fs < T_FUT; fs++) {
#pragma unroll
        for (int lay = 0; lay < 3; lay++) {
            ull acc[16] = {};
            ull hnew[4];
            const bool w = (L == lay) && gate_lane;
            if (w) {
                if (khalf == 0) {
                    ulonglong2 bv = s->bq[lay][j];
#pragma unroll
                    for (int i = 0; i < 8; i++) { acc[i] = bv.x; acc[8 + i] = bv.y; }
                }
                if (lay == 0)      gloop2<26>(s->W1q, s->hdup,      j, khalf * 26, acc);
                else if (lay == 1) gloop2<51>(s->W2q, s->hdup + 1,  j, khalf * 51, acc);
                else               gloop2<51>(s->W3q, s->hdup + 52, j, khalf * 51, acc);
            }
            combine(acc);
            if (w) {
                if (khalf == 0) cellh<0>(acc, creg, hnew);
                else            cellh<4>(acc, creg, hnew);
            }
            __syncthreads();
            if (w) hwrite(&s->hdup[1 + lay * H + j][khalf * 4], hnew);
            __syncthreads();
        }
        if (tid < BB) {
            float v = head_dot(s, tid);
            out[(size_t)(b0 + tid) * T_TOT + T_IN + fs] = v;
            s->hdup[0][tid] = pack2(v);
        }
        __syncthreads();
    }
}

extern "C" void kernel_launch(void *const *d_in, const int *in_sizes, int n_in,
                              void *d_out, int out_size) {
    (void)in_sizes; (void)n_in; (void)out_size;
    cudaFuncSetAttribute(lstm_seq_kernel,
                         cudaFuncAttributeMaxDynamicSharedMemorySize,
                         (int)sizeof(Smem));
    lstm_seq_kernel<<<NCTA, TPB, sizeof(Smem)>>>(
        (const float *)d_in[0],
        (const float *)d_in[1], (const float *)d_in[2],
        (const float *)d_in[3], (const float *)d_in[4],
        (const float *)d_in[5], (const float *)d_in[6],
        (const float *)d_in[7], (const float *)d_in[8],
        (const float *)d_in[9], (const float *)d_in[10],
        (const float *)d_in[11], (const float *)d_in[12],
        (const float *)d_in[13], (const float *)d_in[14],
        (float *)d_out);
}